// round 3
// baseline (speedup 1.0000x reference)
#include <cuda_runtime.h>
#include <cuda_bf16.h>
#include <math.h>

// Problem dims
constexpr int Bn = 4;
constexpr int Sn = 2048;
constexpr int Dn = 768;
constexpr int Un = 768;
constexpr int Mproj = Bn * Sn;   // 8192

// Scratch (device globals: allocation-free per harness rules)
__device__ float g_Q[(size_t)Bn * Sn * Un];
__device__ float g_K[(size_t)Bn * Sn * Un];
__device__ float g_V[(size_t)Bn * Sn * Un];
__device__ float g_KT[(size_t)Bn * Un * Sn];
__device__ float g_P[(size_t)Bn * Sn * Sn];   // scores / probs, 64 MB

// ---------------------------------------------------------------------------
// 128x128x8 SGEMM body. C[M,N] = A[M,K] @ B[K,N], all row-major.
// lda = K, ldb/ldc passed in. Grid: (N/128, M/128). 256 threads.
// Requires M%128==0, N%128==0, K%8==0 (true for all call sites).
// ---------------------------------------------------------------------------
__device__ __forceinline__ void sgemm_body(const float* __restrict__ A,
                                           const float* __restrict__ B,
                                           float* __restrict__ C,
                                           int K, int ldb, int ldc) {
    constexpr int BM = 128, BN = 128, BK = 8, TM = 8, TN = 8;
    __shared__ float As[BK * BM];   // transposed: As[k][m]
    __shared__ float Bs[BK * BN];   // Bs[k][n]

    const int tid = threadIdx.x;
    const int cRow = blockIdx.y;
    const int cCol = blockIdx.x;

    A += (size_t)cRow * BM * K;
    B += (size_t)cCol * BN;
    C += (size_t)cRow * BM * ldc + (size_t)cCol * BN;

    // A tile load mapping: 128 rows x 8 cols, one float4 per thread
    const int aRow = tid >> 1;            // 0..127
    const int aCol = (tid & 1) * 4;       // 0 or 4
    // B tile load mapping: 8 rows x 128 cols, one float4 per thread
    const int bRow = tid >> 5;            // 0..7
    const int bCol = (tid & 31) * 4;      // 0..124

    const int tx = tid & 15;              // 0..15 (cols)
    const int ty = tid >> 4;              // 0..15 (rows)

    float acc[TM][TN];
#pragma unroll
    for (int i = 0; i < TM; i++)
#pragma unroll
        for (int j = 0; j < TN; j++) acc[i][j] = 0.0f;

    for (int k0 = 0; k0 < K; k0 += BK) {
        float4 av = *(const float4*)&A[(size_t)aRow * K + k0 + aCol];
        As[(aCol + 0) * BM + aRow] = av.x;
        As[(aCol + 1) * BM + aRow] = av.y;
        As[(aCol + 2) * BM + aRow] = av.z;
        As[(aCol + 3) * BM + aRow] = av.w;
        float4 bv = *(const float4*)&B[(size_t)(k0 + bRow) * ldb + bCol];
        *(float4*)&Bs[bRow * BN + bCol] = bv;
        __syncthreads();

#pragma unroll
        for (int kk = 0; kk < BK; kk++) {
            float af[TM], bf[TN];
            *(float4*)(af + 0) = *(const float4*)&As[kk * BM + ty * TM + 0];
            *(float4*)(af + 4) = *(const float4*)&As[kk * BM + ty * TM + 4];
            *(float4*)(bf + 0) = *(const float4*)&Bs[kk * BN + tx * TN + 0];
            *(float4*)(bf + 4) = *(const float4*)&Bs[kk * BN + tx * TN + 4];
#pragma unroll
            for (int i = 0; i < TM; i++)
#pragma unroll
                for (int j = 0; j < TN; j++)
                    acc[i][j] = fmaf(af[i], bf[j], acc[i][j]);
        }
        __syncthreads();
    }

#pragma unroll
    for (int i = 0; i < TM; i++) {
        float* crow = &C[(size_t)(ty * TM + i) * ldc + tx * TN];
        float4 v0 = make_float4(acc[i][0], acc[i][1], acc[i][2], acc[i][3]);
        float4 v1 = make_float4(acc[i][4], acc[i][5], acc[i][6], acc[i][7]);
        *(float4*)(crow + 0) = v0;
        *(float4*)(crow + 4) = v1;
    }
}

// ---------------------------------------------------------------------------
// Kernel 1: fused QKV projection. z selects weight/output.
// x:[8192,768] @ W:[768,768] -> {g_Q,g_K,g_V}:[8192,768]
// ---------------------------------------------------------------------------
__global__ __launch_bounds__(256) void proj_kernel(const float* __restrict__ x,
                                                   const float* __restrict__ wq,
                                                   const float* __restrict__ wk,
                                                   const float* __restrict__ wv) {
    const int z = blockIdx.z;
    const float* W = (z == 0) ? wq : (z == 1) ? wk : wv;
    float* C = (z == 0) ? g_Q : (z == 1) ? g_K : g_V;
    sgemm_body(x, W, C, Dn, Un, Un);
}

// ---------------------------------------------------------------------------
// Kernel 2: transpose K[b][s][u] -> KT[b][u][s]
// ---------------------------------------------------------------------------
__global__ void transpose_kernel() {
    __shared__ float tile[32][33];
    const int b = blockIdx.z;
    const float* src = g_K + (size_t)b * Sn * Un;
    float* dst = g_KT + (size_t)b * Un * Sn;
    const int s0 = blockIdx.x * 32;
    const int u0 = blockIdx.y * 32;
    for (int i = threadIdx.y; i < 32; i += 8)
        tile[i][threadIdx.x] = src[(size_t)(s0 + i) * Un + u0 + threadIdx.x];
    __syncthreads();
    for (int i = threadIdx.y; i < 32; i += 8)
        dst[(size_t)(u0 + i) * Sn + s0 + threadIdx.x] = tile[threadIdx.x][i];
}

// ---------------------------------------------------------------------------
// Kernel 3: scores[b] = Q[b] @ KT[b]  -> g_P [2048,2048] per batch
// ---------------------------------------------------------------------------
__global__ __launch_bounds__(256) void scores_kernel() {
    const int b = blockIdx.z;
    sgemm_body(g_Q + (size_t)b * Sn * Un,
               g_KT + (size_t)b * Un * Sn,
               g_P + (size_t)b * Sn * Sn,
               Un, Sn, Sn);
}

// ---------------------------------------------------------------------------
// Kernel 4: row softmax over g_P with scale = 1/sqrt(U). One block per row.
// ---------------------------------------------------------------------------
__global__ __launch_bounds__(256) void softmax_kernel() {
    __shared__ float red[256];
    const size_t row = blockIdx.x;            // 0 .. Bn*Sn-1
    float* p = g_P + row * Sn;
    const float scale = rsqrtf((float)Un);
    const int t = threadIdx.x;

    float v[8];
#pragma unroll
    for (int j = 0; j < 8; j++) v[j] = p[t + j * 256] * scale;

    float m = v[0];
#pragma unroll
    for (int j = 1; j < 8; j++) m = fmaxf(m, v[j]);
    red[t] = m;
    __syncthreads();
    for (int s = 128; s > 0; s >>= 1) {
        if (t < s) red[t] = fmaxf(red[t], red[t + s]);
        __syncthreads();
    }
    m = red[0];
    __syncthreads();

    float sum = 0.0f;
#pragma unroll
    for (int j = 0; j < 8; j++) {
        v[j] = __expf(v[j] - m);
        sum += v[j];
    }
    red[t] = sum;
    __syncthreads();
    for (int s = 128; s > 0; s >>= 1) {
        if (t < s) red[t] += red[t + s];
        __syncthreads();
    }
    const float inv = 1.0f / red[0];

#pragma unroll
    for (int j = 0; j < 8; j++) p[t + j * 256] = v[j] * inv;
}

// ---------------------------------------------------------------------------
// Kernel 5: out[b] = P[b] @ V[b]   [2048,2048]@[2048,768]
// ---------------------------------------------------------------------------
__global__ __launch_bounds__(256) void pv_kernel(float* __restrict__ out) {
    const int b = blockIdx.z;
    sgemm_body(g_P + (size_t)b * Sn * Sn,
               g_V + (size_t)b * Sn * Un,
               out + (size_t)b * Sn * Un,
               Sn, Un, Un);
}

// ---------------------------------------------------------------------------
extern "C" void kernel_launch(void* const* d_in, const int* in_sizes, int n_in,
                              void* d_out, int out_size) {
    const float* x  = (const float*)d_in[0];
    const float* wq = (const float*)d_in[1];
    const float* wk = (const float*)d_in[2];
    const float* wv = (const float*)d_in[3];
    float* out = (float*)d_out;

    // 1) Q,K,V projections (z = 0,1,2)
    proj_kernel<<<dim3(Un / 128, Mproj / 128, 3), 256>>>(x, wq, wk, wv);
    // 2) K -> K^T
    transpose_kernel<<<dim3(Sn / 32, Un / 32, Bn), dim3(32, 8)>>>();
    // 3) scores = Q @ K^T
    scores_kernel<<<dim3(Sn / 128, Sn / 128, Bn), 256>>>();
    // 4) softmax(scores * 1/sqrt(U))
    softmax_kernel<<<Bn * Sn, 256>>>();
    // 5) out = P @ V
    pv_kernel<<<dim3(Un / 128, Sn / 128, Bn), 256>>>(out);
}

// round 4
// speedup vs baseline: 1.6266x; 1.6266x over previous
#include <cuda_runtime.h>
#include <math.h>

constexpr int Bn = 4, Sn = 2048, Dn = 768, Un = 768;
constexpr int Mproj = Bn * Sn;   // 8192

// Scratch (device globals, allocation-free)
__device__ float g_Q[(size_t)Bn * Sn * Un];
__device__ float g_K[(size_t)Bn * Sn * Un];
__device__ float g_V[(size_t)Bn * Sn * Un];
__device__ float g_P[(size_t)Bn * Sn * Sn];   // 64 MB scores/probs

// ---------------------------------------------------------------------------
__device__ __forceinline__ unsigned f2tf(float x) {
    unsigned r;
    asm("cvt.rna.tf32.f32 %0, %1;" : "=r"(r) : "f"(x));
    return r;
}

__device__ __forceinline__ void mma8(float* c, const unsigned* a, const unsigned* b) {
    asm volatile(
        "mma.sync.aligned.m16n8k8.row.col.f32.tf32.tf32.f32 "
        "{%0,%1,%2,%3}, {%4,%5,%6,%7}, {%8,%9}, {%0,%1,%2,%3};\n"
        : "+f"(c[0]), "+f"(c[1]), "+f"(c[2]), "+f"(c[3])
        : "r"(a[0]), "r"(a[1]), "r"(a[2]), "r"(a[3]),
          "r"(b[0]), "r"(b[1]));
}

// ---------------------------------------------------------------------------
// Tensor-core GEMM: C[M,N] = A[M,K] @ B.  A row-major (lda).
// BTRANS=0: B row-major [K,N] (ldb).  BTRANS=1: B row-major [N,K] (ldb) => C = A@B^T.
// SPLIT=1: hi/lo tf32 split (3 mma) for near-fp32 accuracy.
// Block: 256 threads, tile 128x128, BK=16. Grid: (N/128, M/128, batch-ish z handled by caller).
// ---------------------------------------------------------------------------
template<int SPLIT, int BTRANS>
__device__ __forceinline__ void mma_gemm(const float* __restrict__ A,
                                         const float* __restrict__ B,
                                         float* __restrict__ C,
                                         int Kdim, int lda, int ldb, int ldc)
{
    constexpr int NS = SPLIT ? 2 : 1;
    constexpr int PAD = 136;          // floats per k-row: bank = (8k + idx) % 32 -> conflict-free
    constexpr int TILE = 16 * PAD;

    extern __shared__ unsigned sm_u[];
    unsigned* As = sm_u;                    // [2 buf][NS][TILE]
    unsigned* Bs = sm_u + 2 * NS * TILE;    // [2 buf][NS][TILE]

    const int tid  = threadIdx.x;
    const int lane = tid & 31;
    const int warp = tid >> 5;
    const int wm = (warp >> 2) * 64;        // warp row offset (2 warp-rows)
    const int wn = (warp & 3) * 32;         // warp col offset (4 warp-cols)
    const int qr = lane >> 2;               // 0..7
    const int qc = lane & 3;                // 0..3

    const int cm0 = blockIdx.y * 128;
    const int cn0 = blockIdx.x * 128;

    // Global load mappings
    const float* Abase = A + (size_t)(cm0 + (tid >> 1)) * lda + (tid & 1) * 8;
    const float* Bbase;
    if (BTRANS) {
        Bbase = B + (size_t)(cn0 + (tid >> 1)) * ldb + (tid & 1) * 8;
    } else {
        Bbase = B + (size_t)(tid >> 5) * ldb + cn0 + (tid & 31) * 4;
    }

    float4 aL0, aL1, bL0, bL1;

    auto loadG = [&](int t) {
        const float* Ap = Abase + t * 16;
        aL0 = *(const float4*)(Ap);
        aL1 = *(const float4*)(Ap + 4);
        if (BTRANS) {
            const float* Bp = Bbase + t * 16;
            bL0 = *(const float4*)(Bp);
            bL1 = *(const float4*)(Bp + 4);
        } else {
            const float* Bp = Bbase + (size_t)t * 16 * ldb;
            bL0 = *(const float4*)(Bp);
            bL1 = *(const float4*)(Bp + (size_t)8 * ldb);
        }
    };

    auto storeS = [&](int buf) {
        unsigned* Ad = As + buf * NS * TILE;
        unsigned* Bd = Bs + buf * NS * TILE;
        const int ar = tid >> 1;
        const int kb = (tid & 1) * 8;
        float av[8] = {aL0.x, aL0.y, aL0.z, aL0.w, aL1.x, aL1.y, aL1.z, aL1.w};
#pragma unroll
        for (int j = 0; j < 8; j++) {
            float v = av[j];
            unsigned hi = f2tf(v);
            Ad[(kb + j) * PAD + ar] = hi;
            if (SPLIT) {
                unsigned lo = f2tf(v - __uint_as_float(hi));
                Ad[TILE + (kb + j) * PAD + ar] = lo;
            }
        }
        float bv[8] = {bL0.x, bL0.y, bL0.z, bL0.w, bL1.x, bL1.y, bL1.z, bL1.w};
        if (BTRANS) {
            const int br = tid >> 1;   // n index
#pragma unroll
            for (int j = 0; j < 8; j++) {
                float v = bv[j];
                unsigned hi = f2tf(v);
                Bd[(kb + j) * PAD + br] = hi;
                if (SPLIT) {
                    unsigned lo = f2tf(v - __uint_as_float(hi));
                    Bd[TILE + (kb + j) * PAD + br] = lo;
                }
            }
        } else {
            const int bk = tid >> 5;           // 0..7
            const int bn = (tid & 31) * 4;
#pragma unroll
            for (int i = 0; i < 2; i++) {
#pragma unroll
                for (int e = 0; e < 4; e++) {
                    float v = bv[i * 4 + e];
                    unsigned hi = f2tf(v);
                    Bd[(bk + 8 * i) * PAD + bn + e] = hi;
                    if (SPLIT) {
                        unsigned lo = f2tf(v - __uint_as_float(hi));
                        Bd[TILE + (bk + 8 * i) * PAD + bn + e] = lo;
                    }
                }
            }
        }
    };

    float acc[4][4][4];
#pragma unroll
    for (int i = 0; i < 4; i++)
#pragma unroll
        for (int j = 0; j < 4; j++)
#pragma unroll
            for (int r = 0; r < 4; r++) acc[i][j][r] = 0.0f;

    const int nT = Kdim >> 4;
    loadG(0);
    storeS(0);
    __syncthreads();

    for (int t = 0; t < nT; t++) {
        const int cur = t & 1;
        if (t + 1 < nT) loadG(t + 1);

#pragma unroll
        for (int ks = 0; ks < 2; ks++) {
            unsigned af[NS][4][4];
            unsigned bf[NS][4][2];
#pragma unroll
            for (int s = 0; s < NS; s++) {
                const unsigned* Ab = As + (cur * NS + s) * TILE + (ks * 8 + qc) * PAD;
#pragma unroll
                for (int mt = 0; mt < 4; mt++) {
                    const int r = wm + 16 * mt + qr;
                    af[s][mt][0] = Ab[r];
                    af[s][mt][1] = Ab[r + 8];
                    af[s][mt][2] = Ab[4 * PAD + r];
                    af[s][mt][3] = Ab[4 * PAD + r + 8];
                }
                const unsigned* Bb = Bs + (cur * NS + s) * TILE + (ks * 8 + qc) * PAD;
#pragma unroll
                for (int nt = 0; nt < 4; nt++) {
                    const int n = wn + 8 * nt + qr;
                    bf[s][nt][0] = Bb[n];
                    bf[s][nt][1] = Bb[4 * PAD + n];
                }
            }
#pragma unroll
            for (int mt = 0; mt < 4; mt++)
#pragma unroll
                for (int nt = 0; nt < 4; nt++) {
                    mma8(acc[mt][nt], af[0][mt], bf[0][nt]);
                    if (SPLIT) {
                        mma8(acc[mt][nt], af[0][mt], bf[1][nt]);
                        mma8(acc[mt][nt], af[1][mt], bf[0][nt]);
                    }
                }
        }
        if (t + 1 < nT) storeS((t + 1) & 1);
        __syncthreads();
    }

    // Epilogue
    float* Cp = C + (size_t)cm0 * ldc + cn0;
#pragma unroll
    for (int mt = 0; mt < 4; mt++)
#pragma unroll
        for (int nt = 0; nt < 4; nt++) {
            const int r = wm + 16 * mt + qr;
            const int c = wn + 8 * nt + 2 * qc;
            float2 v0 = make_float2(acc[mt][nt][0], acc[mt][nt][1]);
            float2 v1 = make_float2(acc[mt][nt][2], acc[mt][nt][3]);
            *(float2*)&Cp[(size_t)r * ldc + c] = v0;
            *(float2*)&Cp[(size_t)(r + 8) * ldc + c] = v1;
        }
}

// ---------------------------------------------------------------------------
// Kernels
// ---------------------------------------------------------------------------
__global__ __launch_bounds__(256, 1) void proj_kernel(const float* __restrict__ x,
                                                      const float* __restrict__ wq,
                                                      const float* __restrict__ wk,
                                                      const float* __restrict__ wv) {
    const int z = blockIdx.z;
    const float* W = (z == 0) ? wq : (z == 1) ? wk : wv;
    float* O = (z == 0) ? g_Q : (z == 1) ? g_K : g_V;
    mma_gemm<1, 0>(x, W, O, Dn, Dn, Un, Un);
}

__global__ __launch_bounds__(256, 1) void scores_kernel() {
    const int b = blockIdx.z;
    mma_gemm<1, 1>(g_Q + (size_t)b * Sn * Un,
                   g_K + (size_t)b * Sn * Un,
                   g_P + (size_t)b * Sn * Sn,
                   Un, Un, Un, Sn);
}

__global__ __launch_bounds__(256, 1) void pv_kernel(float* __restrict__ out) {
    const int b = blockIdx.z;
    mma_gemm<0, 0>(g_P + (size_t)b * Sn * Sn,
                   g_V + (size_t)b * Sn * Un,
                   out + (size_t)b * Sn * Un,
                   Sn, Sn, Un, Un);
}

__global__ __launch_bounds__(256) void softmax_kernel() {
    __shared__ float red[256];
    const size_t row = blockIdx.x;
    float* p = g_P + row * Sn;
    const float scale = rsqrtf((float)Un);
    const int t = threadIdx.x;

    float v[8];
#pragma unroll
    for (int j = 0; j < 8; j++) v[j] = p[t + j * 256] * scale;

    float m = v[0];
#pragma unroll
    for (int j = 1; j < 8; j++) m = fmaxf(m, v[j]);
    red[t] = m;
    __syncthreads();
    for (int s = 128; s > 0; s >>= 1) {
        if (t < s) red[t] = fmaxf(red[t], red[t + s]);
        __syncthreads();
    }
    m = red[0];
    __syncthreads();

    float sum = 0.0f;
#pragma unroll
    for (int j = 0; j < 8; j++) {
        v[j] = __expf(v[j] - m);
        sum += v[j];
    }
    red[t] = sum;
    __syncthreads();
    for (int s = 128; s > 0; s >>= 1) {
        if (t < s) red[t] += red[t + s];
        __syncthreads();
    }
    const float inv = 1.0f / red[0];

#pragma unroll
    for (int j = 0; j < 8; j++) p[t + j * 256] = v[j] * inv;
}

// ---------------------------------------------------------------------------
extern "C" void kernel_launch(void* const* d_in, const int* in_sizes, int n_in,
                              void* d_out, int out_size) {
    const float* x  = (const float*)d_in[0];
    const float* wq = (const float*)d_in[1];
    const float* wk = (const float*)d_in[2];
    const float* wv = (const float*)d_in[3];
    float* out = (float*)d_out;

    constexpr int SMEM_SPLIT  = 2 * 2 * 2 * 16 * 136 * 4;  // 69632 B
    constexpr int SMEM_SINGLE = 2 * 1 * 2 * 16 * 136 * 4;  // 34816 B

    cudaFuncSetAttribute(proj_kernel,   cudaFuncAttributeMaxDynamicSharedMemorySize, SMEM_SPLIT);
    cudaFuncSetAttribute(scores_kernel, cudaFuncAttributeMaxDynamicSharedMemorySize, SMEM_SPLIT);

    // 1) Q,K,V projections (split-tf32, near-fp32 exact)
    proj_kernel<<<dim3(Un / 128, Mproj / 128, 3), 256, SMEM_SPLIT>>>(x, wq, wk, wv);
    // 2) scores = Q @ K^T (split-tf32; reads K directly, no transpose)
    scores_kernel<<<dim3(Sn / 128, Sn / 128, Bn), 256, SMEM_SPLIT>>>();
    // 3) softmax(scores / sqrt(U))
    softmax_kernel<<<Bn * Sn, 256>>>();
    // 4) out = P @ V (single tf32)
    pv_kernel<<<dim3(Un / 128, Sn / 128, Bn), 256, SMEM_SINGLE>>>(out);
}

// round 8
// speedup vs baseline: 2.5873x; 1.5906x over previous
#include <cuda_runtime.h>
#include <math.h>

constexpr int Bn = 4, Sn = 2048, Dn = 768, Un = 768;
constexpr int Mproj = Bn * Sn;   // 8192

// Scratch (device globals, allocation-free)
__device__ float g_Q[(size_t)Bn * Sn * Un];
__device__ float g_K[(size_t)Bn * Sn * Un];
__device__ float g_V[(size_t)Bn * Sn * Un];
__device__ float g_P[(size_t)Bn * Sn * Sn];   // 64 MB scores/probs

// ---------------------------------------------------------------------------
// helpers
// ---------------------------------------------------------------------------
__device__ __forceinline__ unsigned f2tf(float x) {
    unsigned r;
    asm("cvt.rna.tf32.f32 %0, %1;" : "=r"(r) : "f"(x));
    return r;
}

// Split (v0,v1) into bf16x2 hi word + bf16x2 lo (residual) word.
// Word layout: low 16 bits = v0 (even k), high 16 bits = v1 (odd k).
__device__ __forceinline__ void split_pair(float v0, float v1,
                                           unsigned& whi, unsigned& wlo) {
    asm("cvt.rn.bf16x2.f32 %0, %1, %2;" : "=r"(whi) : "f"(v1), "f"(v0));
    float h0 = __uint_as_float(whi << 16);
    float h1 = __uint_as_float(whi & 0xffff0000u);
    asm("cvt.rn.bf16x2.f32 %0, %1, %2;" : "=r"(wlo) : "f"(v1 - h1), "f"(v0 - h0));
}

__device__ __forceinline__ void mma_bf16(float* c, const unsigned* a, const unsigned* b) {
    asm volatile(
        "mma.sync.aligned.m16n8k16.row.col.f32.bf16.bf16.f32 "
        "{%0,%1,%2,%3}, {%4,%5,%6,%7}, {%8,%9}, {%0,%1,%2,%3};\n"
        : "+f"(c[0]), "+f"(c[1]), "+f"(c[2]), "+f"(c[3])
        : "r"(a[0]), "r"(a[1]), "r"(a[2]), "r"(a[3]), "r"(b[0]), "r"(b[1]));
}

__device__ __forceinline__ void mma_tf32(float* c, const unsigned* a, const unsigned* b) {
    asm volatile(
        "mma.sync.aligned.m16n8k8.row.col.f32.tf32.tf32.f32 "
        "{%0,%1,%2,%3}, {%4,%5,%6,%7}, {%8,%9}, {%0,%1,%2,%3};\n"
        : "+f"(c[0]), "+f"(c[1]), "+f"(c[2]), "+f"(c[3])
        : "r"(a[0]), "r"(a[1]), "r"(a[2]), "r"(a[3]), "r"(b[0]), "r"(b[1]));
}

// ---------------------------------------------------------------------------
// bf16-split GEMM: C[M,N] = A[M,K] @ B (BTRANS=0: B[K,N]; BTRANS=1: B[N,K] => A@B^T)
// fp32 in/out, hi/lo bf16 split (3 x m16n8k16), near-fp32 accuracy.
// 256 threads, tile 128x128, BK=16, double-buffered smem.
// ---------------------------------------------------------------------------
template<int BTRANS>
__device__ __forceinline__ void bf16_gemm(const float* __restrict__ A,
                                          const float* __restrict__ B,
                                          float* __restrict__ C,
                                          int Kdim, int lda, int ldb, int ldc)
{
    constexpr int PAD = 136;        // words per kpair-row (conflict-free fragment loads)
    constexpr int TILE = 8 * PAD;   // one (hi or lo) tile: 8 kpairs x 128(+pad)

    extern __shared__ unsigned sm_u[];   // [2 buf][Ahi,Alo,Bhi,Blo][TILE]

    const int tid  = threadIdx.x;
    const int lane = tid & 31;
    const int warp = tid >> 5;
    const int wm = (warp >> 2) * 64;
    const int wn = (warp & 3) * 32;
    const int qr = lane >> 2;
    const int qc = lane & 3;

    const int cm0 = blockIdx.y * 128;
    const int cn0 = blockIdx.x * 128;

    const float* Abase = A + (size_t)(cm0 + (tid >> 1)) * lda + (tid & 1) * 8;
    const float* Bbase = BTRANS
        ? B + (size_t)(cn0 + (tid >> 1)) * ldb + (tid & 1) * 8
        : B + (size_t)(2 * (tid >> 5)) * ldb + cn0 + (tid & 31) * 4;

    float a_st[8], b_st[8];

    auto loadG = [&](int t) {
        const float* Ap = Abase + t * 16;
        *(float4*)(a_st)     = *(const float4*)(Ap);
        *(float4*)(a_st + 4) = *(const float4*)(Ap + 4);
        if (BTRANS) {
            const float* Bp = Bbase + t * 16;
            *(float4*)(b_st)     = *(const float4*)(Bp);
            *(float4*)(b_st + 4) = *(const float4*)(Bp + 4);
        } else {
            const float* Bp = Bbase + (size_t)t * 16 * ldb;
            *(float4*)(b_st)     = *(const float4*)(Bp);        // row 2kp
            *(float4*)(b_st + 4) = *(const float4*)(Bp + ldb);  // row 2kp+1
        }
    };

    auto storeS = [&](int buf) {
        unsigned* Ahi = sm_u + buf * 4 * TILE;
        unsigned* Alo = Ahi + TILE;
        unsigned* Bhi = Alo + TILE;
        unsigned* Blo = Bhi + TILE;
        const int ar  = tid >> 1;
        const int kp0 = (tid & 1) * 4;
#pragma unroll
        for (int j = 0; j < 4; j++) {
            unsigned whi, wlo;
            split_pair(a_st[2 * j], a_st[2 * j + 1], whi, wlo);
            Ahi[(kp0 + j) * PAD + ar] = whi;
            Alo[(kp0 + j) * PAD + ar] = wlo;
        }
        if (BTRANS) {
            const int br = tid >> 1;
#pragma unroll
            for (int j = 0; j < 4; j++) {
                unsigned whi, wlo;
                split_pair(b_st[2 * j], b_st[2 * j + 1], whi, wlo);
                Bhi[(kp0 + j) * PAD + br] = whi;
                Blo[(kp0 + j) * PAD + br] = wlo;
            }
        } else {
            const int kp = tid >> 5;
            const int c  = (tid & 31) * 4;
            unsigned whi[4], wlo[4];
#pragma unroll
            for (int e = 0; e < 4; e++)
                split_pair(b_st[e], b_st[4 + e], whi[e], wlo[e]);  // (row 2kp, row 2kp+1)
            *(uint4*)&Bhi[kp * PAD + c] = make_uint4(whi[0], whi[1], whi[2], whi[3]);
            *(uint4*)&Blo[kp * PAD + c] = make_uint4(wlo[0], wlo[1], wlo[2], wlo[3]);
        }
    };

    float acc[4][4][4];
#pragma unroll
    for (int i = 0; i < 4; i++)
#pragma unroll
        for (int j = 0; j < 4; j++)
#pragma unroll
            for (int r = 0; r < 4; r++) acc[i][j][r] = 0.0f;

    const int nT = Kdim >> 4;
    loadG(0);
    storeS(0);
    __syncthreads();

    for (int t = 0; t < nT; t++) {
        const int cur = t & 1;
        if (t + 1 < nT) loadG(t + 1);

        const unsigned* Ahi = sm_u + cur * 4 * TILE;
        const unsigned* Alo = Ahi + TILE;
        const unsigned* Bhi = Alo + TILE;
        const unsigned* Blo = Bhi + TILE;

        unsigned a[4][4], bh[4][2], bl[4][2];

        // load A_hi, B_hi
#pragma unroll
        for (int mt = 0; mt < 4; mt++) {
            const int r = wm + 16 * mt + qr;
            a[mt][0] = Ahi[qc * PAD + r];
            a[mt][1] = Ahi[qc * PAD + r + 8];
            a[mt][2] = Ahi[(qc + 4) * PAD + r];
            a[mt][3] = Ahi[(qc + 4) * PAD + r + 8];
        }
#pragma unroll
        for (int nt = 0; nt < 4; nt++) {
            const int n = wn + 8 * nt + qr;
            bh[nt][0] = Bhi[qc * PAD + n];
            bh[nt][1] = Bhi[(qc + 4) * PAD + n];
        }
        // hi * hi
#pragma unroll
        for (int mt = 0; mt < 4; mt++)
#pragma unroll
            for (int nt = 0; nt < 4; nt++) mma_bf16(acc[mt][nt], a[mt], bh[nt]);

        // hi * lo
#pragma unroll
        for (int nt = 0; nt < 4; nt++) {
            const int n = wn + 8 * nt + qr;
            bl[nt][0] = Blo[qc * PAD + n];
            bl[nt][1] = Blo[(qc + 4) * PAD + n];
        }
#pragma unroll
        for (int mt = 0; mt < 4; mt++)
#pragma unroll
            for (int nt = 0; nt < 4; nt++) mma_bf16(acc[mt][nt], a[mt], bl[nt]);

        // lo * hi (overwrite A regs)
#pragma unroll
        for (int mt = 0; mt < 4; mt++) {
            const int r = wm + 16 * mt + qr;
            a[mt][0] = Alo[qc * PAD + r];
            a[mt][1] = Alo[qc * PAD + r + 8];
            a[mt][2] = Alo[(qc + 4) * PAD + r];
            a[mt][3] = Alo[(qc + 4) * PAD + r + 8];
        }
#pragma unroll
        for (int mt = 0; mt < 4; mt++)
#pragma unroll
            for (int nt = 0; nt < 4; nt++) mma_bf16(acc[mt][nt], a[mt], bh[nt]);

        if (t + 1 < nT) storeS(cur ^ 1);
        __syncthreads();
    }

    float* Cp = C + (size_t)cm0 * ldc + cn0;
#pragma unroll
    for (int mt = 0; mt < 4; mt++)
#pragma unroll
        for (int nt = 0; nt < 4; nt++) {
            const int r = wm + 16 * mt + qr;
            const int c = wn + 8 * nt + 2 * qc;
            *(float2*)&Cp[(size_t)r * ldc + c]       = make_float2(acc[mt][nt][0], acc[mt][nt][1]);
            *(float2*)&Cp[(size_t)(r + 8) * ldc + c] = make_float2(acc[mt][nt][2], acc[mt][nt][3]);
        }
}

// ---------------------------------------------------------------------------
// tf32 single GEMM (for P@V): C[M,N] = A[M,K] @ B[K,N]
// ---------------------------------------------------------------------------
__device__ __forceinline__ void tf32_gemm(const float* __restrict__ A,
                                          const float* __restrict__ B,
                                          float* __restrict__ C,
                                          int Kdim, int lda, int ldb, int ldc)
{
    constexpr int PAD = 136;
    constexpr int TILE = 16 * PAD;       // words: 16 k x 128(+pad)

    extern __shared__ unsigned sm_u[];   // [2 buf][A,B][TILE]

    const int tid  = threadIdx.x;
    const int lane = tid & 31;
    const int warp = tid >> 5;
    const int wm = (warp >> 2) * 64;
    const int wn = (warp & 3) * 32;
    const int qr = lane >> 2;
    const int qc = lane & 3;

    const int cm0 = blockIdx.y * 128;
    const int cn0 = blockIdx.x * 128;

    const float* Abase = A + (size_t)(cm0 + (tid >> 1)) * lda + (tid & 1) * 8;
    const float* Bbase = B + (size_t)(tid >> 5) * ldb + cn0 + (tid & 31) * 4;

    float a_st[8], b_st[8];

    auto loadG = [&](int t) {
        const float* Ap = Abase + t * 16;
        *(float4*)(a_st)     = *(const float4*)(Ap);
        *(float4*)(a_st + 4) = *(const float4*)(Ap + 4);
        const float* Bp = Bbase + (size_t)t * 16 * ldb;
        *(float4*)(b_st)     = *(const float4*)(Bp);                   // row bk
        *(float4*)(b_st + 4) = *(const float4*)(Bp + (size_t)8 * ldb); // row bk+8
    };

    auto storeS = [&](int buf) {
        unsigned* As = sm_u + buf * 2 * TILE;
        unsigned* Bs = As + TILE;
        const int ar = tid >> 1;
        const int kb = (tid & 1) * 8;
#pragma unroll
        for (int j = 0; j < 8; j++)
            As[(kb + j) * PAD + ar] = f2tf(a_st[j]);
        const int bk = tid >> 5;
        const int c  = (tid & 31) * 4;
        unsigned w0[4], w1[4];
#pragma unroll
        for (int e = 0; e < 4; e++) { w0[e] = f2tf(b_st[e]); w1[e] = f2tf(b_st[4 + e]); }
        *(uint4*)&Bs[bk * PAD + c]       = make_uint4(w0[0], w0[1], w0[2], w0[3]);
        *(uint4*)&Bs[(bk + 8) * PAD + c] = make_uint4(w1[0], w1[1], w1[2], w1[3]);
    };

    float acc[4][4][4];
#pragma unroll
    for (int i = 0; i < 4; i++)
#pragma unroll
        for (int j = 0; j < 4; j++)
#pragma unroll
            for (int r = 0; r < 4; r++) acc[i][j][r] = 0.0f;

    const int nT = Kdim >> 4;
    loadG(0);
    storeS(0);
    __syncthreads();

    for (int t = 0; t < nT; t++) {
        const int cur = t & 1;
        if (t + 1 < nT) loadG(t + 1);

        const unsigned* As = sm_u + cur * 2 * TILE;
        const unsigned* Bs = As + TILE;

#pragma unroll
        for (int ks = 0; ks < 2; ks++) {
            unsigned a[4][4], b[4][2];
            const unsigned* Ab = As + (ks * 8 + qc) * PAD;
            const unsigned* Bb = Bs + (ks * 8 + qc) * PAD;
#pragma unroll
            for (int mt = 0; mt < 4; mt++) {
                const int r = wm + 16 * mt + qr;
                a[mt][0] = Ab[r];
                a[mt][1] = Ab[r + 8];
                a[mt][2] = Ab[4 * PAD + r];
                a[mt][3] = Ab[4 * PAD + r + 8];
            }
#pragma unroll
            for (int nt = 0; nt < 4; nt++) {
                const int n = wn + 8 * nt + qr;
                b[nt][0] = Bb[n];
                b[nt][1] = Bb[4 * PAD + n];
            }
#pragma unroll
            for (int mt = 0; mt < 4; mt++)
#pragma unroll
                for (int nt = 0; nt < 4; nt++) mma_tf32(acc[mt][nt], a[mt], b[nt]);
        }

        if (t + 1 < nT) storeS(cur ^ 1);
        __syncthreads();
    }

    float* Cp = C + (size_t)cm0 * ldc + cn0;
#pragma unroll
    for (int mt = 0; mt < 4; mt++)
#pragma unroll
        for (int nt = 0; nt < 4; nt++) {
            const int r = wm + 16 * mt + qr;
            const int c = wn + 8 * nt + 2 * qc;
            *(float2*)&Cp[(size_t)r * ldc + c]       = make_float2(acc[mt][nt][0], acc[mt][nt][1]);
            *(float2*)&Cp[(size_t)(r + 8) * ldc + c] = make_float2(acc[mt][nt][2], acc[mt][nt][3]);
        }
}

// ---------------------------------------------------------------------------
// Kernels
// ---------------------------------------------------------------------------
__global__ __launch_bounds__(256, 2) void proj_kernel(const float* __restrict__ x,
                                                      const float* __restrict__ wq,
                                                      const float* __restrict__ wk,
                                                      const float* __restrict__ wv) {
    const int z = blockIdx.z;
    const float* W = (z == 0) ? wq : (z == 1) ? wk : wv;
    float* O = (z == 0) ? g_Q : (z == 1) ? g_K : g_V;
    bf16_gemm<0>(x, W, O, Dn, Dn, Un, Un);
}

__global__ __launch_bounds__(256, 2) void scores_kernel() {
    const int b = blockIdx.z;
    bf16_gemm<1>(g_Q + (size_t)b * Sn * Un,
                 g_K + (size_t)b * Sn * Un,
                 g_P + (size_t)b * Sn * Sn,
                 Un, Un, Un, Sn);
}

__global__ __launch_bounds__(256, 2) void pv_kernel(float* __restrict__ out) {
    const int b = blockIdx.z;
    tf32_gemm(g_P + (size_t)b * Sn * Sn,
              g_V + (size_t)b * Sn * Un,
              out + (size_t)b * Sn * Un,
              Sn, Sn, Un, Un);
}

// Row softmax, scale folded in. Warp-shuffle reductions (8 warps/row).
__global__ __launch_bounds__(256) void softmax_kernel() {
    __shared__ float red[8];
    const size_t row = blockIdx.x;
    float* p = g_P + row * Sn;
    const float scale = rsqrtf((float)Un);
    const int t = threadIdx.x;
    const int lane = t & 31;
    const int warp = t >> 5;

    float v[8];
#pragma unroll
    for (int j = 0; j < 8; j++) v[j] = p[t + j * 256] * scale;

    float m = v[0];
#pragma unroll
    for (int j = 1; j < 8; j++) m = fmaxf(m, v[j]);
#pragma unroll
    for (int s = 16; s > 0; s >>= 1)
        m = fmaxf(m, __shfl_xor_sync(0xffffffffu, m, s));
    if (lane == 0) red[warp] = m;
    __syncthreads();
    m = red[lane & 7];
#pragma unroll
    for (int s = 4; s > 0; s >>= 1)
        m = fmaxf(m, __shfl_xor_sync(0xffffffffu, m, s));

    float sum = 0.0f;
#pragma unroll
    for (int j = 0; j < 8; j++) {
        v[j] = __expf(v[j] - m);
        sum += v[j];
    }
#pragma unroll
    for (int s = 16; s > 0; s >>= 1)
        sum += __shfl_xor_sync(0xffffffffu, sum, s);
    __syncthreads();           // red reuse guard
    if (lane == 0) red[warp] = sum;
    __syncthreads();
    sum = red[lane & 7];
#pragma unroll
    for (int s = 4; s > 0; s >>= 1)
        sum += __shfl_xor_sync(0xffffffffu, sum, s);
    const float inv = 1.0f / sum;

#pragma unroll
    for (int j = 0; j < 8; j++) p[t + j * 256] = v[j] * inv;
}

// ---------------------------------------------------------------------------
extern "C" void kernel_launch(void* const* d_in, const int* in_sizes, int n_in,
                              void* d_out, int out_size) {
    const float* x  = (const float*)d_in[0];
    const float* wq = (const float*)d_in[1];
    const float* wk = (const float*)d_in[2];
    const float* wv = (const float*)d_in[3];
    float* out = (float*)d_out;

    constexpr int SMEM_BF16 = 2 * 4 * 8 * 136 * 4;   // 34816 B
    constexpr int SMEM_TF32 = 2 * 2 * 16 * 136 * 4;  // 34816 B

    // 1) Q,K,V projections (bf16-split, near-fp32 exact)
    proj_kernel<<<dim3(Un / 128, Mproj / 128, 3), 256, SMEM_BF16>>>(x, wq, wk, wv);
    // 2) scores = Q @ K^T (bf16-split)
    scores_kernel<<<dim3(Sn / 128, Sn / 128, Bn), 256, SMEM_BF16>>>();
    // 3) softmax(scores / sqrt(U))
    softmax_kernel<<<Bn * Sn, 256>>>();
    // 4) out = P @ V (tf32 single)
    pv_kernel<<<dim3(Un / 128, Sn / 128, Bn), 256, SMEM_TF32>>>(out);
}

// round 15
// speedup vs baseline: 3.0392x; 1.1747x over previous
#include <cuda_runtime.h>
#include <math.h>
#include <stdint.h>

constexpr int Bn = 4, Sn = 2048, Dn = 768, Un = 768;
constexpr int Mproj = Bn * Sn;   // 8192

// ---------------------------------------------------------------------------
// Device-global scratch (allocation-free). bf16 as unsigned short, pre-split.
// ---------------------------------------------------------------------------
__device__ unsigned short g_Xhi[(size_t)Mproj * Dn];
__device__ unsigned short g_Xlo[(size_t)Mproj * Dn];
__device__ unsigned short g_Whi[(size_t)3 * Dn * Un];   // W [z][d][u] natural
__device__ unsigned short g_Wlo[(size_t)3 * Dn * Un];
__device__ unsigned short g_Qhi[(size_t)Mproj * Un];
__device__ unsigned short g_Qlo[(size_t)Mproj * Un];
__device__ unsigned short g_Khi[(size_t)Mproj * Un];
__device__ unsigned short g_Klo[(size_t)Mproj * Un];
__device__ unsigned short g_Vhi[(size_t)Mproj * Un];    // V [b][s][u] natural
__device__ unsigned short g_Vlo[(size_t)Mproj * Un];
__device__ float          g_P  [(size_t)Bn * Sn * Sn];  // fp32 scores
__device__ unsigned short g_Phi[(size_t)Bn * Sn * Sn];  // probs hi/lo
__device__ unsigned short g_Plo[(size_t)Bn * Sn * Sn];

// ---------------------------------------------------------------------------
// helpers
// ---------------------------------------------------------------------------
__device__ __forceinline__ uint32_t smem_u32(const void* p) {
    uint32_t a;
    asm("{ .reg .u64 t; cvta.to.shared.u64 t, %1; cvt.u32.u64 %0, t; }"
        : "=r"(a) : "l"(p));
    return a;
}

// Split (v0,v1) -> bf16x2 hi word + bf16x2 residual word.
// low 16 bits = v0 (even k), high 16 bits = v1 (odd k).
__device__ __forceinline__ void split_pair(float v0, float v1,
                                           uint32_t& whi, uint32_t& wlo) {
    asm("cvt.rn.bf16x2.f32 %0, %1, %2;" : "=r"(whi) : "f"(v1), "f"(v0));
    float h0 = __uint_as_float(whi << 16);
    float h1 = __uint_as_float(whi & 0xffff0000u);
    asm("cvt.rn.bf16x2.f32 %0, %1, %2;" : "=r"(wlo) : "f"(v1 - h1), "f"(v0 - h0));
}

__device__ __forceinline__ void mma_bf16(float* c, const uint32_t* a, const uint32_t* b) {
    asm volatile(
        "mma.sync.aligned.m16n8k16.row.col.f32.bf16.bf16.f32 "
        "{%0,%1,%2,%3}, {%4,%5,%6,%7}, {%8,%9}, {%0,%1,%2,%3};\n"
        : "+f"(c[0]), "+f"(c[1]), "+f"(c[2]), "+f"(c[3])
        : "r"(a[0]), "r"(a[1]), "r"(a[2]), "r"(a[3]), "r"(b[0]), "r"(b[1]));
}

__device__ __forceinline__ void cp16(uint32_t d, const void* s) {
    asm volatile("cp.async.cg.shared.global [%0], [%1], 16;"
                 :: "r"(d), "l"(s) : "memory");
}
__device__ __forceinline__ void cp_commit() {
    asm volatile("cp.async.commit_group;" ::: "memory");
}

__device__ __forceinline__ void ldsm4(uint32_t& r0, uint32_t& r1,
                                      uint32_t& r2, uint32_t& r3, uint32_t a) {
    asm volatile("ldmatrix.sync.aligned.m8n8.x4.shared.b16 {%0,%1,%2,%3}, [%4];"
                 : "=r"(r0), "=r"(r1), "=r"(r2), "=r"(r3) : "r"(a));
}
__device__ __forceinline__ void ldsm4t(uint32_t& r0, uint32_t& r1,
                                       uint32_t& r2, uint32_t& r3, uint32_t a) {
    asm volatile("ldmatrix.sync.aligned.m8n8.x4.trans.shared.b16 {%0,%1,%2,%3}, [%4];"
                 : "=r"(r0), "=r"(r1), "=r"(r2), "=r"(r3) : "r"(a));
}

// ---------------------------------------------------------------------------
// Split-bf16 GEMM body (3-term: hh + hl + lh).
// C[128,128] = (Ahi+Alo)[128,K] @ B, accumulated in acc[4][4][4] (fp32 frags).
// BTRANS=0: B is [n][k] rows-along-k (plain ldmatrix).
// BTRANS=1: B is [k][n] rows-along-n (ldmatrix.trans)  => C = A @ B.
// 256 threads, BK=32, cp.async double-buffered smem (2 x 32KB).
// Tile layouts (XOR-swizzled, 16B units):
//   nontrans: addr = row*64  + ((u ^ ((row>>1)&3)) << 4), u = k/8 in 0..3
//   trans:    addr = k*256   + ((u ^ (k&7))        << 4), u = n/8 in 0..15
// ---------------------------------------------------------------------------
template<int BTRANS>
__device__ __forceinline__ void gemm_body(const unsigned short* __restrict__ ahi,
                                          const unsigned short* __restrict__ alo,
                                          const unsigned short* __restrict__ bhi,
                                          const unsigned short* __restrict__ blo,
                                          int lda, int ldb, int K,
                                          float acc[4][4][4])
{
    extern __shared__ char sm[];
    const uint32_t smb = smem_u32(sm);
    const int tid  = threadIdx.x;
    const int lane = tid & 31;
    const int warp = tid >> 5;
    const int wm = (warp >> 2) * 64;
    const int wn = (warp & 3) * 32;

#pragma unroll
    for (int i = 0; i < 4; i++)
#pragma unroll
        for (int j = 0; j < 4; j++)
#pragma unroll
            for (int r = 0; r < 4; r++) acc[i][j][r] = 0.0f;

    // ---- cp.async mappings (2 x 16B per thread per tile) ----
    const int nr = tid >> 1;             // nontrans row 0..127
    const int nu = (tid & 1) * 2;        // nontrans first 16B unit
    const uint32_t dA0 = nr * 64 + (((nu    ) ^ ((nr >> 1) & 3)) << 4);
    const uint32_t dA1 = nr * 64 + (((nu + 1) ^ ((nr >> 1) & 3)) << 4);
    const unsigned short* sAh = ahi + (size_t)nr * lda + nu * 8;
    const unsigned short* sAl = alo + (size_t)nr * lda + nu * 8;

    uint32_t dB0, dB1;
    const unsigned short *sBh, *sBl;
    if (BTRANS) {
        const int kr = tid >> 3;         // 0..31
        const int un = (tid & 7) * 2;    // 0..14
        dB0 = kr * 256 + (((un    ) ^ (kr & 7)) << 4);
        dB1 = kr * 256 + (((un + 1) ^ (kr & 7)) << 4);
        sBh = bhi + (size_t)kr * ldb + un * 8;
        sBl = blo + (size_t)kr * ldb + un * 8;
    } else {
        dB0 = dA0; dB1 = dA1;
        sBh = bhi + (size_t)nr * ldb + nu * 8;
        sBl = blo + (size_t)nr * ldb + nu * 8;
    }

    auto issue = [&](int t, int buf) {
        const uint32_t b = smb + buf * 32768;
        const size_t ao = (size_t)t * 32;
        cp16(b         + dA0, sAh + ao);
        cp16(b         + dA1, sAh + ao + 8);
        cp16(b + 8192  + dA0, sAl + ao);
        cp16(b + 8192  + dA1, sAl + ao + 8);
        const size_t bo = BTRANS ? (size_t)t * 32 * ldb : (size_t)t * 32;
        cp16(b + 16384 + dB0, sBh + bo);
        cp16(b + 16384 + dB1, sBh + bo + 8);
        cp16(b + 24576 + dB0, sBl + bo);
        cp16(b + 24576 + dB1, sBl + bo + 8);
        cp_commit();
    };

    // ---- ldmatrix per-lane address components ----
    const int idx   = lane & 7;
    const int aRow  = idx + ((lane >> 3) & 1) * 8;   // A frag row offset
    const int aDu   = lane >> 4;                     // A frag u offset
    const int bnRow = idx + (lane >> 4) * 8;         // B nontrans row offset
    const int bnDu  = (lane >> 3) & 1;
    const int btRow = idx + ((lane >> 3) & 1) * 8;   // B trans k-row offset
    const int btDu  = lane >> 4;                     // B trans n-unit offset

    const int nT = K >> 5;
    issue(0, 0);

    for (int t = 0; t < nT; t++) {
        if (t + 1 < nT) {
            issue(t + 1, (t + 1) & 1);
            asm volatile("cp.async.wait_group 1;" ::: "memory");
        } else {
            asm volatile("cp.async.wait_group 0;" ::: "memory");
        }
        __syncthreads();

        const uint32_t Ah = smb + (t & 1) * 32768;
        const uint32_t Al = Ah + 8192;
        const uint32_t Bh = Ah + 16384;
        const uint32_t Bl = Ah + 24576;

#pragma unroll
        for (int s = 0; s < 2; s++) {
            uint32_t a[4][4], bh[4][2], bl[4][2];

            // A hi fragments
#pragma unroll
            for (int mt = 0; mt < 4; mt++) {
                const int row = wm + 16 * mt + aRow;
                const int u = 2 * s + aDu;
                ldsm4(a[mt][0], a[mt][1], a[mt][2], a[mt][3],
                      Ah + row * 64 + ((u ^ ((row >> 1) & 3)) << 4));
            }
            // B hi fragments
            if (BTRANS) {
#pragma unroll
                for (int g = 0; g < 2; g++) {
                    const int row = 16 * s + btRow;
                    const int u = ((wn + 16 * g) >> 3) + btDu;
                    ldsm4t(bh[2*g][0], bh[2*g][1], bh[2*g+1][0], bh[2*g+1][1],
                           Bh + row * 256 + ((u ^ (row & 7)) << 4));
                }
            } else {
#pragma unroll
                for (int g = 0; g < 2; g++) {
                    const int row = wn + 16 * g + bnRow;
                    const int u = 2 * s + bnDu;
                    ldsm4(bh[2*g][0], bh[2*g][1], bh[2*g+1][0], bh[2*g+1][1],
                          Bh + row * 64 + ((u ^ ((row >> 1) & 3)) << 4));
                }
            }
            // hi * hi
#pragma unroll
            for (int mt = 0; mt < 4; mt++)
#pragma unroll
                for (int nt = 0; nt < 4; nt++) mma_bf16(acc[mt][nt], a[mt], bh[nt]);

            // B lo fragments, hi * lo
            if (BTRANS) {
#pragma unroll
                for (int g = 0; g < 2; g++) {
                    const int row = 16 * s + btRow;
                    const int u = ((wn + 16 * g) >> 3) + btDu;
                    ldsm4t(bl[2*g][0], bl[2*g][1], bl[2*g+1][0], bl[2*g+1][1],
                           Bl + row * 256 + ((u ^ (row & 7)) << 4));
                }
            } else {
#pragma unroll
                for (int g = 0; g < 2; g++) {
                    const int row = wn + 16 * g + bnRow;
                    const int u = 2 * s + bnDu;
                    ldsm4(bl[2*g][0], bl[2*g][1], bl[2*g+1][0], bl[2*g+1][1],
                          Bl + row * 64 + ((u ^ ((row >> 1) & 3)) << 4));
                }
            }
#pragma unroll
            for (int mt = 0; mt < 4; mt++)
#pragma unroll
                for (int nt = 0; nt < 4; nt++) mma_bf16(acc[mt][nt], a[mt], bl[nt]);

            // A lo (reuse regs), lo * hi
#pragma unroll
            for (int mt = 0; mt < 4; mt++) {
                const int row = wm + 16 * mt + aRow;
                const int u = 2 * s + aDu;
                ldsm4(a[mt][0], a[mt][1], a[mt][2], a[mt][3],
                      Al + row * 64 + ((u ^ ((row >> 1) & 3)) << 4));
            }
#pragma unroll
            for (int mt = 0; mt < 4; mt++)
#pragma unroll
                for (int nt = 0; nt < 4; nt++) mma_bf16(acc[mt][nt], a[mt], bh[nt]);
        }
        __syncthreads();
    }
}

// ---------------------------------------------------------------------------
// Prep kernels: elementwise split to bf16 hi/lo
// ---------------------------------------------------------------------------
__global__ __launch_bounds__(256) void prep_x_kernel(const float* __restrict__ x) {
    const size_t i = ((size_t)blockIdx.x * 256 + threadIdx.x) * 8;
    float4 v0 = *(const float4*)(x + i);
    float4 v1 = *(const float4*)(x + i + 4);
    uint32_t h[4], l[4];
    split_pair(v0.x, v0.y, h[0], l[0]);
    split_pair(v0.z, v0.w, h[1], l[1]);
    split_pair(v1.x, v1.y, h[2], l[2]);
    split_pair(v1.z, v1.w, h[3], l[3]);
    *(uint4*)(g_Xhi + i) = make_uint4(h[0], h[1], h[2], h[3]);
    *(uint4*)(g_Xlo + i) = make_uint4(l[0], l[1], l[2], l[3]);
}

__global__ __launch_bounds__(256) void prep_w_kernel(const float* __restrict__ wq,
                                                     const float* __restrict__ wk,
                                                     const float* __restrict__ wv) {
    const int z = blockIdx.y;
    const float* W = (z == 0) ? wq : (z == 1) ? wk : wv;
    const size_t i = ((size_t)blockIdx.x * 256 + threadIdx.x) * 8;
    const size_t o = (size_t)z * Dn * Un + i;
    float4 v0 = *(const float4*)(W + i);
    float4 v1 = *(const float4*)(W + i + 4);
    uint32_t h[4], l[4];
    split_pair(v0.x, v0.y, h[0], l[0]);
    split_pair(v0.z, v0.w, h[1], l[1]);
    split_pair(v1.x, v1.y, h[2], l[2]);
    split_pair(v1.z, v1.w, h[3], l[3]);
    *(uint4*)(g_Whi + o) = make_uint4(h[0], h[1], h[2], h[3]);
    *(uint4*)(g_Wlo + o) = make_uint4(l[0], l[1], l[2], l[3]);
}

// ---------------------------------------------------------------------------
// GEMM kernels
// ---------------------------------------------------------------------------
constexpr int SMEM_GB = 2 * 32768;   // 64 KB

__global__ __launch_bounds__(256, 2) void proj_kernel() {
    const int z  = blockIdx.z;
    const int m0 = blockIdx.y * 128;
    const int n0 = blockIdx.x * 128;
    float acc[4][4][4];
    gemm_body<1>(g_Xhi + (size_t)m0 * Dn, g_Xlo + (size_t)m0 * Dn,
                 g_Whi + (size_t)z * Dn * Un + n0,
                 g_Wlo + (size_t)z * Dn * Un + n0,
                 Dn, Un, Dn, acc);

    unsigned short* ohi = (z == 0) ? g_Qhi : (z == 1) ? g_Khi : g_Vhi;
    unsigned short* olo = (z == 0) ? g_Qlo : (z == 1) ? g_Klo : g_Vlo;
    const int lane = threadIdx.x & 31, warp = threadIdx.x >> 5;
    const int wm = (warp >> 2) * 64, wn = (warp & 3) * 32;
    const int qr = lane >> 2, qc = lane & 3;
#pragma unroll
    for (int mt = 0; mt < 4; mt++)
#pragma unroll
        for (int nt = 0; nt < 4; nt++) {
            const int r = wm + 16 * mt + qr;
            const int c = wn + 8 * nt + 2 * qc;
            uint32_t h, l;
            split_pair(acc[mt][nt][0], acc[mt][nt][1], h, l);
            *(uint32_t*)(ohi + (size_t)(m0 + r) * Un + n0 + c) = h;
            *(uint32_t*)(olo + (size_t)(m0 + r) * Un + n0 + c) = l;
            split_pair(acc[mt][nt][2], acc[mt][nt][3], h, l);
            *(uint32_t*)(ohi + (size_t)(m0 + r + 8) * Un + n0 + c) = h;
            *(uint32_t*)(olo + (size_t)(m0 + r + 8) * Un + n0 + c) = l;
        }
}

__global__ __launch_bounds__(256, 2) void scores_kernel() {
    const int b  = blockIdx.z;
    const int m0 = blockIdx.y * 128;
    const int n0 = blockIdx.x * 128;
    float acc[4][4][4];
    gemm_body<0>(g_Qhi + ((size_t)b * Sn + m0) * Un, g_Qlo + ((size_t)b * Sn + m0) * Un,
                 g_Khi + ((size_t)b * Sn + n0) * Un, g_Klo + ((size_t)b * Sn + n0) * Un,
                 Un, Un, Un, acc);

    const int lane = threadIdx.x & 31, warp = threadIdx.x >> 5;
    const int wm = (warp >> 2) * 64, wn = (warp & 3) * 32;
    const int qr = lane >> 2, qc = lane & 3;
    float* Cp = g_P + ((size_t)b * Sn + m0) * Sn + n0;
#pragma unroll
    for (int mt = 0; mt < 4; mt++)
#pragma unroll
        for (int nt = 0; nt < 4; nt++) {
            const int r = wm + 16 * mt + qr;
            const int c = wn + 8 * nt + 2 * qc;
            *(float2*)&Cp[(size_t)r * Sn + c]       = make_float2(acc[mt][nt][0], acc[mt][nt][1]);
            *(float2*)&Cp[(size_t)(r + 8) * Sn + c] = make_float2(acc[mt][nt][2], acc[mt][nt][3]);
        }
}

__global__ __launch_bounds__(256, 2) void pv_kernel(float* __restrict__ out) {
    const int b  = blockIdx.z;
    const int m0 = blockIdx.y * 128;
    const int n0 = blockIdx.x * 128;
    float acc[4][4][4];
    gemm_body<1>(g_Phi + ((size_t)b * Sn + m0) * Sn, g_Plo + ((size_t)b * Sn + m0) * Sn,
                 g_Vhi + (size_t)b * Sn * Un + n0,   g_Vlo + (size_t)b * Sn * Un + n0,
                 Sn, Un, Sn, acc);

    const int lane = threadIdx.x & 31, warp = threadIdx.x >> 5;
    const int wm = (warp >> 2) * 64, wn = (warp & 3) * 32;
    const int qr = lane >> 2, qc = lane & 3;
    float* Cp = out + ((size_t)b * Sn + m0) * Un + n0;
#pragma unroll
    for (int mt = 0; mt < 4; mt++)
#pragma unroll
        for (int nt = 0; nt < 4; nt++) {
            const int r = wm + 16 * mt + qr;
            const int c = wn + 8 * nt + 2 * qc;
            *(float2*)&Cp[(size_t)r * Un + c]       = make_float2(acc[mt][nt][0], acc[mt][nt][1]);
            *(float2*)&Cp[(size_t)(r + 8) * Un + c] = make_float2(acc[mt][nt][2], acc[mt][nt][3]);
        }
}

// ---------------------------------------------------------------------------
// Softmax: fp32 scores -> split bf16 probs. One block per row.
// ---------------------------------------------------------------------------
__global__ __launch_bounds__(256) void softmax_kernel() {
    __shared__ float red[8];
    const size_t row = blockIdx.x;
    const float* p = g_P + row * Sn;
    unsigned short* phi = g_Phi + row * Sn;
    unsigned short* plo = g_Plo + row * Sn;
    const float scale = rsqrtf((float)Un);
    const int t = threadIdx.x;
    const int lane = t & 31;
    const int warp = t >> 5;

    float v[8];
    *(float4*)(v)     = *(const float4*)(p + 8 * t);
    *(float4*)(v + 4) = *(const float4*)(p + 8 * t + 4);
#pragma unroll
    for (int j = 0; j < 8; j++) v[j] *= scale;

    float m = v[0];
#pragma unroll
    for (int j = 1; j < 8; j++) m = fmaxf(m, v[j]);
#pragma unroll
    for (int s = 16; s > 0; s >>= 1)
        m = fmaxf(m, __shfl_xor_sync(0xffffffffu, m, s));
    if (lane == 0) red[warp] = m;
    __syncthreads();
    m = red[lane & 7];
#pragma unroll
    for (int s = 4; s > 0; s >>= 1)
        m = fmaxf(m, __shfl_xor_sync(0xffffffffu, m, s));

    float sum = 0.0f;
#pragma unroll
    for (int j = 0; j < 8; j++) {
        v[j] = __expf(v[j] - m);
        sum += v[j];
    }
#pragma unroll
    for (int s = 16; s > 0; s >>= 1)
        sum += __shfl_xor_sync(0xffffffffu, sum, s);
    __syncthreads();
    if (lane == 0) red[warp] = sum;
    __syncthreads();
    sum = red[lane & 7];
#pragma unroll
    for (int s = 4; s > 0; s >>= 1)
        sum += __shfl_xor_sync(0xffffffffu, sum, s);
    const float inv = 1.0f / sum;

    uint32_t h[4], l[4];
#pragma unroll
    for (int e = 0; e < 4; e++)
        split_pair(v[2 * e] * inv, v[2 * e + 1] * inv, h[e], l[e]);
    *(uint4*)(phi + 8 * t) = make_uint4(h[0], h[1], h[2], h[3]);
    *(uint4*)(plo + 8 * t) = make_uint4(l[0], l[1], l[2], l[3]);
}

// ---------------------------------------------------------------------------
extern "C" void kernel_launch(void* const* d_in, const int* in_sizes, int n_in,
                              void* d_out, int out_size) {
    const float* x  = (const float*)d_in[0];
    const float* wq = (const float*)d_in[1];
    const float* wk = (const float*)d_in[2];
    const float* wv = (const float*)d_in[3];
    float* out = (float*)d_out;

    cudaFuncSetAttribute(proj_kernel,   cudaFuncAttributeMaxDynamicSharedMemorySize, SMEM_GB);
    cudaFuncSetAttribute(scores_kernel, cudaFuncAttributeMaxDynamicSharedMemorySize, SMEM_GB);
    cudaFuncSetAttribute(pv_kernel,     cudaFuncAttributeMaxDynamicSharedMemorySize, SMEM_GB);

    // 1) split inputs to bf16 hi/lo
    prep_x_kernel<<<(int)((size_t)Mproj * Dn / 8 / 256), 256>>>(x);
    prep_w_kernel<<<dim3(Dn * Un / 8 / 256, 3), 256>>>(wq, wk, wv);
    // 2) Q,K,V projections (split bf16, B=W natural layout via ldmatrix.trans)
    proj_kernel<<<dim3(Un / 128, Mproj / 128, 3), 256, SMEM_GB>>>();
    // 3) scores = Q @ K^T (split bf16) -> fp32
    scores_kernel<<<dim3(Sn / 128, Sn / 128, Bn), 256, SMEM_GB>>>();
    // 4) softmax -> split bf16 probs
    softmax_kernel<<<Bn * Sn, 256>>>();
    // 5) out = P @ V (split bf16, B=V natural layout via ldmatrix.trans)
    pv_kernel<<<dim3(Un / 128, Sn / 128, Bn), 256, SMEM_GB>>>(out);
}